// round 15
// baseline (speedup 1.0000x reference)
#include <cuda_runtime.h>
#include <cuda_bf16.h>
#include <mma.h>
#include <stdint.h>

using namespace nvcuda;

#define S_LEN 1024
#define NHEADS 64
#define NT 512
#define NKT 16
#define LB 72   // bf16 leading dim (64+8)
#define LF 72   // fp32 leading dim

// smem byte offsets; bf16 tile = 64*72*2 = 9216 B, fp32 tile = 18432 B
#define QRH 0
#define QRL 9216
#define QIH 18432
#define QIL 27648
#define KRH 36864
#define KRL 46080
#define KIH 55296
#define KIL 64512
#define KNH 73728
#define KNL 82944
#define PRH 36864      // P region aliases K region (never live together)
#define PRL 46080
#define PIH 55296
#define PIL 64512
#define URO 73728
#define UIO 82944
#define VRH 92160
#define VRL 101376
#define VIH 110592
#define VIL 119808
#define VNH 129024
#define VNL 138240
#define SRO 147456     // scores fp32
#define SIO 165888
#define OAR 147456     // final accum stores alias S and P regions
#define OAI 165888
#define OBR 36864
#define OBI 55296
#define RMN 184320     // [8][64] fp32 partials
#define RMX 186368
#define SMEM_BYTES 188416

#define BF(off) ((__nv_bfloat16*)(smc + (off)))
#define FP(off) ((float*)(smc + (off)))

typedef wmma::fragment<wmma::matrix_a, 16, 16, 16, __nv_bfloat16, wmma::row_major> FragA;
typedef wmma::fragment<wmma::matrix_b, 16, 16, 16, __nv_bfloat16, wmma::col_major> FragBc;
typedef wmma::fragment<wmma::matrix_b, 16, 16, 16, __nv_bfloat16, wmma::row_major> FragBr;
typedef wmma::fragment<wmma::accumulator, 16, 16, 16, float> FragC;

__device__ __forceinline__ uint2 h4(float4 v) {
    __nv_bfloat162 a = __floats2bfloat162_rn(v.x, v.y);
    __nv_bfloat162 b = __floats2bfloat162_rn(v.z, v.w);
    uint2 r; r.x = *(uint32_t*)&a; r.y = *(uint32_t*)&b; return r;
}
__device__ __forceinline__ float4 resid(float4 v, uint2 h) {
    __nv_bfloat162 a = *(__nv_bfloat162*)&h.x, b = *(__nv_bfloat162*)&h.y;
    return make_float4(v.x - __bfloat162float(a.x), v.y - __bfloat162float(a.y),
                       v.z - __bfloat162float(b.x), v.w - __bfloat162float(b.y));
}
__device__ __forceinline__ uint2 neg2(uint2 v) {
    return make_uint2(v.x ^ 0x80008000u, v.y ^ 0x80008000u);
}

__global__ void __launch_bounds__(NT)
cvattn_wm(const float* __restrict__ qr_g, const float* __restrict__ qi_g,
          const float* __restrict__ kr_g, const float* __restrict__ ki_g,
          const float* __restrict__ vr_g, const float* __restrict__ vi_g,
          float* __restrict__ out)
{
    extern __shared__ char smc[];
    const int tid = threadIdx.x;
    const int wid = tid >> 5;
    const int fr  = wid >> 2;            // frag row 0..3 (16 q each)
    const int fc  = wid & 3;             // frag col 0..3 (16 k/d each)
    const int qt = blockIdx.x, head = blockIdx.y;
    const long hb = (long)head * S_LEN * 64;

    // ---- load Q (scaled 1/8), split hi/lo bf16, row-major [q][d] ----
#pragma unroll
    for (int it = 0; it < 2; ++it) {
        int c = it * NT + tid;                 // 1024 float4 chunks
        int q = c >> 4, d4 = (c & 15) << 2;
        long g = hb + (long)(qt * 64 + q) * 64 + d4;
        float4 r4 = *(const float4*)(qr_g + g);
        float4 i4 = *(const float4*)(qi_g + g);
        r4.x *= 0.125f; r4.y *= 0.125f; r4.z *= 0.125f; r4.w *= 0.125f;
        i4.x *= 0.125f; i4.y *= 0.125f; i4.z *= 0.125f; i4.w *= 0.125f;
        int idx = q * LB + d4;
        uint2 h = h4(r4);
        *(uint2*)(BF(QRH) + idx) = h;
        *(uint2*)(BF(QRL) + idx) = h4(resid(r4, h));
        h = h4(i4);
        *(uint2*)(BF(QIH) + idx) = h;
        *(uint2*)(BF(QIL) + idx) = h4(resid(i4, h));
    }

    FragC ar, ai, br, bi;
    wmma::fill_fragment(ar, 0.f); wmma::fill_fragment(ai, 0.f);
    wmma::fill_fragment(br, 0.f); wmma::fill_fragment(bi, 0.f);
    float mnp = 3.0e38f, mxp = -3.0e38f;
    const int erow = tid >> 3, eseg = tid & 7;   // (q row, 8-col segment)

#pragma unroll 1
    for (int kt = 0; kt < NKT; ++kt) {
        __syncthreads();   // prev PV frag loads done before K/P/V overwrite

        // ---- load K (+kn=-ki) and V (+vn=-vi), split hi/lo, [k][d] row-major ----
        long kb = hb + (long)(kt * 64) * 64;
#pragma unroll
        for (int it = 0; it < 2; ++it) {
            int c = it * NT + tid;
            int k = c >> 4, d4 = (c & 15) << 2;
            long g = kb + (long)k * 64 + d4;
            int idx = k * LB + d4;
            float4 r4 = *(const float4*)(kr_g + g);
            float4 i4 = *(const float4*)(ki_g + g);
            uint2 h = h4(r4);
            *(uint2*)(BF(KRH) + idx) = h;
            *(uint2*)(BF(KRL) + idx) = h4(resid(r4, h));
            h = h4(i4);
            *(uint2*)(BF(KIH) + idx) = h;
            *(uint2*)(BF(KNH) + idx) = neg2(h);
            uint2 hl = h4(resid(i4, h));
            *(uint2*)(BF(KIL) + idx) = hl;
            *(uint2*)(BF(KNL) + idx) = neg2(hl);
            r4 = *(const float4*)(vr_g + g);
            i4 = *(const float4*)(vi_g + g);
            h = h4(r4);
            *(uint2*)(BF(VRH) + idx) = h;
            *(uint2*)(BF(VRL) + idx) = h4(resid(r4, h));
            h = h4(i4);
            *(uint2*)(BF(VIH) + idx) = h;
            *(uint2*)(BF(VNH) + idx) = neg2(h);
            hl = h4(resid(i4, h));
            *(uint2*)(BF(VIL) + idx) = hl;
            *(uint2*)(BF(VNL) + idx) = neg2(hl);
        }
        __syncthreads();

        // ---- scores: sr = qr*kr + qi*(-ki), si = qr*ki + qi*kr (split 3-term) ----
        {
            FragC s_r, s_i;
            wmma::fill_fragment(s_r, 0.f);
            wmma::fill_fragment(s_i, 0.f);
#pragma unroll
            for (int ks = 0; ks < 4; ++ks) {
                const int ao = fr * 16 * LB + ks * 16;
                const int bo = fc * 16 * LB + ks * 16;   // K^T col_major
                FragA aqrh, aqrl, aqih, aqil;
                wmma::load_matrix_sync(aqrh, BF(QRH) + ao, LB);
                wmma::load_matrix_sync(aqrl, BF(QRL) + ao, LB);
                wmma::load_matrix_sync(aqih, BF(QIH) + ao, LB);
                wmma::load_matrix_sync(aqil, BF(QIL) + ao, LB);
                {   // group by B frag to cap live registers
                    FragBc b0, b1;
                    wmma::load_matrix_sync(b0, BF(KRH) + bo, LB);
                    wmma::load_matrix_sync(b1, BF(KRL) + bo, LB);
                    wmma::mma_sync(s_r, aqrh, b0, s_r);
                    wmma::mma_sync(s_r, aqrl, b0, s_r);
                    wmma::mma_sync(s_r, aqrh, b1, s_r);
                    wmma::mma_sync(s_i, aqih, b0, s_i);
                    wmma::mma_sync(s_i, aqil, b0, s_i);
                    wmma::mma_sync(s_i, aqih, b1, s_i);
                }
                {
                    FragBc b0, b1;
                    wmma::load_matrix_sync(b0, BF(KIH) + bo, LB);
                    wmma::load_matrix_sync(b1, BF(KIL) + bo, LB);
                    wmma::mma_sync(s_i, aqrh, b0, s_i);
                    wmma::mma_sync(s_i, aqrl, b0, s_i);
                    wmma::mma_sync(s_i, aqrh, b1, s_i);
                }
                {
                    FragBc b0, b1;
                    wmma::load_matrix_sync(b0, BF(KNH) + bo, LB);
                    wmma::load_matrix_sync(b1, BF(KNL) + bo, LB);
                    wmma::mma_sync(s_r, aqih, b0, s_r);
                    wmma::mma_sync(s_r, aqil, b0, s_r);
                    wmma::mma_sync(s_r, aqih, b1, s_r);
                }
            }
            const int so = fr * 16 * LF + fc * 16;
            wmma::store_matrix_sync(FP(SRO) + so, s_r, LF, wmma::mem_row_major);
            wmma::store_matrix_sync(FP(SIO) + so, s_i, LF, wmma::mem_row_major);
        }
        __syncthreads();

        // ---- epilogue: mag, running min/max (register), split-P + U to smem ----
        {
            const float* srp = FP(SRO) + erow * LF + eseg * 8;
            const float* sip = FP(SIO) + erow * LF + eseg * 8;
            const int pb = erow * LB + eseg * 8;
#pragma unroll
            for (int i = 0; i < 2; ++i) {
                float4 a4 = *(const float4*)(srp + 4 * i);
                float4 b4 = *(const float4*)(sip + 4 * i);
                float4 ur4, ui4;
                float m2, rv, mg;
#define DOEL(X) m2 = fmaf(a4.X, a4.X, b4.X * b4.X); m2 = fmaxf(m2, 1e-37f); \
                rv = rsqrtf(m2); mg = m2 * rv; mnp = fminf(mnp, mg); mxp = fmaxf(mxp, mg); \
                ur4.X = a4.X * rv; ui4.X = b4.X * rv;
                DOEL(x) DOEL(y) DOEL(z) DOEL(w)
#undef DOEL
                uint2 h = h4(a4);
                *(uint2*)(BF(PRH) + pb + 4 * i) = h;
                *(uint2*)(BF(PRL) + pb + 4 * i) = h4(resid(a4, h));
                h = h4(b4);
                *(uint2*)(BF(PIH) + pb + 4 * i) = h;
                *(uint2*)(BF(PIL) + pb + 4 * i) = h4(resid(b4, h));
                *(uint2*)(BF(URO) + pb + 4 * i) = h4(ur4);
                *(uint2*)(BF(UIO) + pb + 4 * i) = h4(ui4);
            }
        }
        __syncthreads();

        // ---- PV: A += P*V (split), B += U*V (bf16), grouped by B frag ----
#pragma unroll
        for (int ks = 0; ks < 4; ++ks) {
            const int ao = fr * 16 * LB + ks * 16;
            const int bo = ks * 16 * LB + fc * 16;   // V row_major
            FragA aprh, aprl, apih, apil, aur, aui;
            wmma::load_matrix_sync(aprh, BF(PRH) + ao, LB);
            wmma::load_matrix_sync(aprl, BF(PRL) + ao, LB);
            wmma::load_matrix_sync(apih, BF(PIH) + ao, LB);
            wmma::load_matrix_sync(apil, BF(PIL) + ao, LB);
            wmma::load_matrix_sync(aur,  BF(URO) + ao, LB);
            wmma::load_matrix_sync(aui,  BF(UIO) + ao, LB);
            {
                FragBr b0, b1;
                wmma::load_matrix_sync(b0, BF(VRH) + bo, LB);
                wmma::load_matrix_sync(b1, BF(VRL) + bo, LB);
                wmma::mma_sync(ar, aprh, b0, ar);
                wmma::mma_sync(ar, aprl, b0, ar);
                wmma::mma_sync(ar, aprh, b1, ar);
                wmma::mma_sync(ai, apih, b0, ai);
                wmma::mma_sync(ai, apil, b0, ai);
                wmma::mma_sync(ai, apih, b1, ai);
                wmma::mma_sync(br, aur, b0, br);
                wmma::mma_sync(bi, aui, b0, bi);
            }
            {
                FragBr b0, b1;
                wmma::load_matrix_sync(b0, BF(VIH) + bo, LB);
                wmma::load_matrix_sync(b1, BF(VIL) + bo, LB);
                wmma::mma_sync(ai, aprh, b0, ai);
                wmma::mma_sync(ai, aprl, b0, ai);
                wmma::mma_sync(ai, aprh, b1, ai);
                wmma::mma_sync(bi, aur, b0, bi);
            }
            {
                FragBr b0, b1;
                wmma::load_matrix_sync(b0, BF(VNH) + bo, LB);
                wmma::load_matrix_sync(b1, BF(VNL) + bo, LB);
                wmma::mma_sync(ar, apih, b0, ar);
                wmma::mma_sync(ar, apil, b0, ar);
                wmma::mma_sync(ar, apih, b1, ar);
                wmma::mma_sync(br, aui, b0, br);
            }
        }
    }
    __syncthreads();   // all PV loads done before aliased accum stores

    // ---- store accumulators + min/max partials ----
    {
        const int so = fr * 16 * LF + fc * 16;
        wmma::store_matrix_sync(FP(OAR) + so, ar, LF, wmma::mem_row_major);
        wmma::store_matrix_sync(FP(OAI) + so, ai, LF, wmma::mem_row_major);
        wmma::store_matrix_sync(FP(OBR) + so, br, LF, wmma::mem_row_major);
        wmma::store_matrix_sync(FP(OBI) + so, bi, LF, wmma::mem_row_major);
    }
    FP(RMN)[eseg * 64 + erow] = mnp;
    FP(RMX)[eseg * 64 + erow] = mxp;
    __syncthreads();
    if (tid < 64) {   // combine 8 partials -> slot 0
        float mn = FP(RMN)[tid], mx = FP(RMX)[tid];
#pragma unroll
        for (int j = 1; j < 8; ++j) {
            mn = fminf(mn, FP(RMN)[j * 64 + tid]);
            mx = fmaxf(mx, FP(RMX)[j * 64 + tid]);
        }
        FP(RMN)[tid] = mn;
        FP(RMX)[tid] = 1.0f / (mx - mn);
    }
    __syncthreads();

    // ---- final: out = (A - mn*B)/(mx - mn), coalesced ----
    float* out_r = out;
    float* out_i = out + (long)NHEADS * S_LEN * 64;
#pragma unroll
    for (int it = 0; it < 2; ++it) {
        int c = it * NT + tid;
        int row = c >> 4, c4 = (c & 15) << 2;
        float mn = FP(RMN)[row];
        float isc = FP(RMX)[row];
        float4 A_r = *(const float4*)(FP(OAR) + row * LF + c4);
        float4 A_i = *(const float4*)(FP(OAI) + row * LF + c4);
        float4 B_r = *(const float4*)(FP(OBR) + row * LF + c4);
        float4 B_i = *(const float4*)(FP(OBI) + row * LF + c4);
        float4 o_r, o_i;
        o_r.x = (A_r.x - mn * B_r.x) * isc; o_r.y = (A_r.y - mn * B_r.y) * isc;
        o_r.z = (A_r.z - mn * B_r.z) * isc; o_r.w = (A_r.w - mn * B_r.w) * isc;
        o_i.x = (A_i.x - mn * B_i.x) * isc; o_i.y = (A_i.y - mn * B_i.y) * isc;
        o_i.z = (A_i.z - mn * B_i.z) * isc; o_i.w = (A_i.w - mn * B_i.w) * isc;
        long g = hb + (long)(qt * 64 + row) * 64 + c4;
        *(float4*)(out_r + g) = o_r;
        *(float4*)(out_i + g) = o_i;
    }
}

extern "C" void kernel_launch(void* const* d_in, const int* in_sizes, int n_in,
                              void* d_out, int out_size)
{
    const float* qr = (const float*)d_in[0];
    const float* qi = (const float*)d_in[1];
    const float* kr = (const float*)d_in[2];
    const float* ki = (const float*)d_in[3];
    const float* vr = (const float*)d_in[4];
    const float* vi = (const float*)d_in[5];
    float* out = (float*)d_out;

    cudaFuncSetAttribute(cvattn_wm, cudaFuncAttributeMaxDynamicSharedMemorySize, SMEM_BYTES);
    dim3 grid(S_LEN / 64, NHEADS);   // 16 q-tiles x 64 heads
    cvattn_wm<<<grid, NT, SMEM_BYTES>>>(qr, qi, kr, ki, vr, vi, out);
}